// round 13
// baseline (speedup 1.0000x reference)
#include <cuda_runtime.h>
#include <cuda_bf16.h>
#include <cuda_fp16.h>
#include <math.h>
#include <cstdint>

// ---------------------------------------------------------------------------
// Problem constants
// ---------------------------------------------------------------------------
#define NN   50000
#define EE   200000
#define F0   512

// Layer 1: A = [x(512)|0|agg1(512)|0|pad] -> KH=1088 (idx cols zeroed, handled
// exactly in epilogue). A stored as plain fp16; W split fp16 hi/lo.
#define KH   1088
#define OUT1 256

// Layer 2: A2 = [h1(256)|idx(1)|agg2(257)|pad(62)] -> KH2=576, split bf16 x3.
#define KH2  576
#define KT2  (2*KH2)
#define OUT2 64

// fp32 h1' buffer for agg2 gather: [h1(256)|idx(1)] stride 260
#define H1S  260

#define NEG_SLOPE 0.01f

// ---------------------------------------------------------------------------
// Scratch (static device globals)
// ---------------------------------------------------------------------------
__device__ __align__(256) __half g_a1h[(size_t)NN * KH];            // ~109 MB
__device__ __align__(256) __half g_w1h[(size_t)OUT1 * 2 * KH];      // hi at k, lo at KH+k
__device__ __align__(256) __half2 g_pq[(size_t)NN * F0];            // (exp(x), x*exp(x)) ~102 MB
__device__ __align__(256) __nv_bfloat16 g_a2bf[(size_t)NN * KT2];   // ~115 MB
__device__ __align__(256) __nv_bfloat16 g_w2bf[(size_t)OUT2 * KT2];
__device__ __align__(256) float g_h1[(size_t)NN * H1S];             // ~52 MB
__device__ __align__(256) float g_h2[(size_t)NN * OUT2];            // ~13 MB
__device__ __align__(256) float g_aggidx[NN];
__device__ int g_counts[NN];
__device__ int g_cursor[NN];
__device__ int g_offsets[NN + 1];
__device__ int g_csr[EE];
__device__ int g_blocksum[256];
__device__ int g_blockoff[256];
__device__ int g_idx_is32;

// ---------------------------------------------------------------------------
// Helpers
// ---------------------------------------------------------------------------
__device__ __forceinline__ uint32_t smem_u32(const void* p) {
    uint32_t a;
    asm("{ .reg .u64 t; cvta.to.shared.u64 t, %1; cvt.u32.u64 %0, t; }" : "=r"(a) : "l"(p));
    return a;
}

#define SW128(off) ((off) ^ (((off) >> 3) & 0x70))

__device__ __forceinline__ void ldmx4(uint32_t r[4], uint32_t addr) {
    asm volatile("ldmatrix.sync.aligned.m8n8.x4.shared.b16 {%0,%1,%2,%3}, [%4];"
        : "=r"(r[0]), "=r"(r[1]), "=r"(r[2]), "=r"(r[3]) : "r"(addr));
}

__device__ __forceinline__ void mma_bf16(float c[4], const uint32_t a[4], const uint32_t b[2]) {
    asm volatile("mma.sync.aligned.m16n8k16.row.col.f32.bf16.bf16.f32 "
        "{%0,%1,%2,%3}, {%4,%5,%6,%7}, {%8,%9}, {%0,%1,%2,%3};"
        : "+f"(c[0]), "+f"(c[1]), "+f"(c[2]), "+f"(c[3])
        : "r"(a[0]), "r"(a[1]), "r"(a[2]), "r"(a[3]), "r"(b[0]), "r"(b[1]));
}

__device__ __forceinline__ void mma_f16(float c[4], const uint32_t a[4], const uint32_t b[2]) {
    asm volatile("mma.sync.aligned.m16n8k16.row.col.f32.f16.f16.f32 "
        "{%0,%1,%2,%3}, {%4,%5,%6,%7}, {%8,%9}, {%0,%1,%2,%3};"
        : "+f"(c[0]), "+f"(c[1]), "+f"(c[2]), "+f"(c[3])
        : "r"(a[0]), "r"(a[1]), "r"(a[2]), "r"(a[3]), "r"(b[0]), "r"(b[1]));
}

__device__ __forceinline__ void cp16(uint32_t saddr, const void* gaddr, int nbytes) {
    asm volatile("cp.async.cg.shared.global [%0], [%1], 16, %2;"
        :: "r"(saddr), "l"(gaddr), "r"(nbytes));
}
#define CP_COMMIT() asm volatile("cp.async.commit_group;" ::: "memory")
#define CP_WAIT(n)  asm volatile("cp.async.wait_group %0;" :: "n"(n) : "memory")

__device__ __forceinline__ void bf16_split(float v, __nv_bfloat16& hi, __nv_bfloat16& lo) {
    hi = __float2bfloat16(v);
    lo = __float2bfloat16(v - __bfloat162float(hi));
}

__device__ __forceinline__ void f16_split(float v, __half& hi, __half& lo) {
    hi = __float2half(v);
    lo = __float2half(v - __half2float(hi));
}

// inclusive block scan over 256 threads; warp_part must be __shared__ int[8]
__device__ __forceinline__ int block_incl_scan_256(int v, int* warp_part) {
    int lane = threadIdx.x & 31, w = threadIdx.x >> 5;
    int x = v;
#pragma unroll
    for (int o = 1; o < 32; o <<= 1) {
        int u = __shfl_up_sync(0xffffffffu, x, o);
        if (lane >= o) x += u;
    }
    if (lane == 31) warp_part[w] = x;
    __syncthreads();
    if (w == 0) {
        int y = (lane < 8) ? warp_part[lane] : 0;
#pragma unroll
        for (int o = 1; o < 8; o <<= 1) {
            int u = __shfl_up_sync(0xffffffffu, y, o);
            if (lane >= o) y += u;
        }
        if (lane < 8) warp_part[lane] = y;
    }
    __syncthreads();
    return x + ((w > 0) ? warp_part[w - 1] : 0);
}

// ---------------------------------------------------------------------------
// edge_index dtype detection (int64 vs int32-demoted)
// ---------------------------------------------------------------------------
__global__ void detect_kernel(const int* ei_words) {
    __shared__ int acc;
    if (threadIdx.x == 0) acc = 0;
    __syncthreads();
    int v = ei_words[2 * threadIdx.x + 1];
    if (v != 0) atomicOr(&acc, 1);
    __syncthreads();
    if (threadIdx.x == 0) g_idx_is32 = acc;
}

__device__ __forceinline__ int edge_val(const void* ei, int idx) {
    if (g_idx_is32) return ((const int*)ei)[idx];
    return (int)((const long long*)ei)[idx];
}

// ---------------------------------------------------------------------------
// PQ precompute: g_pq[n][f] = (exp(x), x*exp(x)) in fp16x2.
// exp is hoisted out of the per-edge loop: 25.6M exps instead of 102.4M.
// ---------------------------------------------------------------------------
__global__ void pq_kernel(const float* __restrict__ x) {
    int idx = blockIdx.x * blockDim.x + threadIdx.x;
    if (idx >= NN * F0) return;
    float v  = x[idx];
    float ev = __expf(v);
    g_pq[idx] = __floats2half2_rn(ev, ev * v);
}

// ---------------------------------------------------------------------------
// CSR build (by destination)
// ---------------------------------------------------------------------------
__global__ void zero_kernel() {
    int i = blockIdx.x * blockDim.x + threadIdx.x;
    if (i < NN) { g_counts[i] = 0; g_cursor[i] = 0; }
}

__global__ void hist_kernel(const void* ei) {
    int e = blockIdx.x * blockDim.x + threadIdx.x;
    if (e >= EE) return;
    int d = edge_val(ei, EE + e);
    if ((unsigned)d < NN) atomicAdd(&g_counts[d], 1);
}

#define SCAN_B 196   // ceil(50000/256)

__global__ void scan1_kernel() {
    __shared__ int wp[8];
    int i = blockIdx.x * 256 + threadIdx.x;
    int v = (i < NN) ? g_counts[i] : 0;
    int incl = block_incl_scan_256(v, wp);
    if (threadIdx.x == 255) g_blocksum[blockIdx.x] = incl;
}

__global__ void scan2_kernel() {
    __shared__ int wp[8];
    int t = threadIdx.x;
    int v = (t < SCAN_B) ? g_blocksum[t] : 0;
    int incl = block_incl_scan_256(v, wp);
    if (t < SCAN_B) g_blockoff[t] = incl - v;
    if (t == 255) g_offsets[NN] = incl;
}

__global__ void scan3_kernel() {
    __shared__ int wp[8];
    int i = blockIdx.x * 256 + threadIdx.x;
    int v = (i < NN) ? g_counts[i] : 0;
    int incl = block_incl_scan_256(v, wp);
    if (i < NN) g_offsets[i] = incl - v + g_blockoff[blockIdx.x];
}

__global__ void scatter_kernel(const void* ei) {
    int e = blockIdx.x * blockDim.x + threadIdx.x;
    if (e >= EE) return;
    int s = edge_val(ei, e);
    int d = edge_val(ei, EE + e);
    if ((unsigned)d >= NN) return;
    int pos = g_offsets[d] + atomicAdd(&g_cursor[d], 1);
    g_csr[pos] = s;
}

// ---------------------------------------------------------------------------
// Weight prep
// ---------------------------------------------------------------------------
__global__ void wsplit1_kernel(const float* __restrict__ W1_root,
                               const float* __restrict__ W1_rel) {
    int idx = blockIdx.x * blockDim.x + threadIdx.x;
    if (idx >= OUT1 * KH) return;
    int n = idx / KH, k = idx - n * KH;
    float w = 0.f;
    if (k < 513)       w = W1_root[k * OUT1 + n];
    else if (k < 1026) w = W1_rel[(k - 513) * OUT1 + n];
    __half hi, lo;
    f16_split(w, hi, lo);
    g_w1h[(size_t)n * (2 * KH) + k]      = hi;
    g_w1h[(size_t)n * (2 * KH) + KH + k] = lo;
}

__global__ void wsplit2_kernel(const float* __restrict__ W2_root,
                               const float* __restrict__ W2_rel) {
    int idx = blockIdx.x * blockDim.x + threadIdx.x;
    if (idx >= OUT2 * KH2) return;
    int n = idx / KH2, k = idx - n * KH2;
    float w = 0.f;
    if (k < 257)      w = W2_root[k * OUT2 + n];
    else if (k < 514) w = W2_rel[(k - 257) * OUT2 + n];
    __nv_bfloat16 hi, lo;
    bf16_split(w, hi, lo);
    g_w2bf[(size_t)n * KT2 + k]       = hi;
    g_w2bf[(size_t)n * KT2 + KH2 + k] = lo;
}

__global__ void node_prep_kernel() {
    int i = blockIdx.x * blockDim.x + threadIdx.x;
    if (i >= NN) return;
    g_h1[(size_t)i * H1S + 256] = (float)i;
    __nv_bfloat16 hi, lo;
    bf16_split((float)i, hi, lo);
    __nv_bfloat16* r = g_a2bf + (size_t)i * KT2;
    r[256] = hi; r[KH2 + 256] = lo;
    __nv_bfloat16 z = __float2bfloat16(0.f);
#pragma unroll
    for (int p = 514; p < KH2; p++) { r[p] = z; r[KH2 + p] = z; }
}

// ---------------------------------------------------------------------------
// Aggregation 1: per-destination softmax aggregation over 513 features.
// Uses precomputed PQ: d = sum P, num = sum Q, out = num/d — NO exp in the
// edge loop (1 coalesced half2 load + 2 FADD per feature).
// Index feature (values up to 5e4) keeps an online-max form on lane 0.
// Emits fp16 A1 row [x|0|agg|0|pad] and fp32 g_aggidx.
// ---------------------------------------------------------------------------
__global__ void agg1_kernel(const float* __restrict__ x) {
    int gid  = blockIdx.x * blockDim.x + threadIdx.x;
    int node = gid >> 5;
    int lane = gid & 31;
    if (node >= NN) return;

    int beg = g_offsets[node], end = g_offsets[node + 1];

    float d[16], num[16];
#pragma unroll
    for (int r = 0; r < 16; r++) { d[r] = 0.f; num[r] = 0.f; }
    float mi = -1e30f, di = 0.f, numi = 0.f;   // index feature (lane 0)

    for (int e = beg; e < end; e++) {
        int s = g_csr[e];
        const __half2* pr = g_pq + (size_t)s * F0;
#pragma unroll
        for (int r = 0; r < 16; r++) {
            float2 w = __half22float2(__ldg(&pr[lane + 32 * r]));
            d[r]  += w.x;
            num[r] += w.y;
        }
        if (lane == 0) {
            float v  = (float)s;
            float nm = fmaxf(mi, v);
            float sc = __expf(mi - nm);
            float ev = __expf(v - nm);
            di   = di   * sc + ev;
            numi = numi * sc + ev * v;
            mi   = nm;
        }
    }

    __half* row = g_a1h + (size_t)node * KH;
    const float* xi = x + (size_t)node * F0;
#pragma unroll
    for (int r = 0; r < 16; r++) {
        int f = lane + 32 * r;
        row[f] = __float2half(xi[f]);
    }
    bool nonempty = (end > beg);
#pragma unroll
    for (int r = 0; r < 16; r++) {
        int f = lane + 32 * r;
        float o = nonempty ? (num[r] / fmaxf(d[r], 1e-16f)) : 0.f;
        row[513 + f] = __float2half(o);
    }
    if (lane == 0) {
        float o = nonempty ? (numi / fmaxf(di, 1e-16f)) : 0.f;
        g_aggidx[node] = o;
        row[512]  = __float2half(0.f);
        row[1025] = __float2half(0.f);
    }
    __half z = __float2half(0.f);
    for (int f = 1026 + lane; f < KH; f += 32) row[f] = z;
}

// ---------------------------------------------------------------------------
// gemm1 (mma.sync fp16x2, double-buffered cp.async):
// h1 = leaky(A1*W1 + b1 + node*W_root[512] + aggidx*W_rel[512]).
// A plain fp16, B split hi/lo; 2 MMA passes: A*Bh + A*Bl.
// CTA 128x128, 8 warps (4m x 2n), BK=64 (17 chunks).
// ---------------------------------------------------------------------------
#define S1_A  0
#define S1_BH 16384
#define S1_BL 32768
#define BUF1  49152
#define SMEM_G1 (2 * BUF1)

__device__ __forceinline__ void g1_prefetch(uint32_t base, int bm0, int bn0,
                                            int k0, int tid) {
#pragma unroll
    for (int t = 0; t < 4; t++) {
        int item = tid + t * 256;
        int r = item >> 3, q = item & 7;
        int grow = bm0 + r;
        int ok = (grow < NN) ? 16 : 0;
        int crow = (grow < NN) ? grow : (NN - 1);
        const char* p = (const char*)(g_a1h + (size_t)crow * KH + k0 + q * 8);
        cp16(base + S1_A + SW128(r * 128 + q * 16), p, ok);
    }
#pragma unroll
    for (int t = 0; t < 4; t++) {
        int item = tid + t * 256;
        int n = item >> 3, q = item & 7;
        const char* p = (const char*)(g_w1h + (size_t)(bn0 + n) * (2 * KH) + k0 + q * 8);
        uint32_t so = SW128(n * 128 + q * 16);
        cp16(base + S1_BH + so, p, 16);
        cp16(base + S1_BL + so, p + KH * 2, 16);
    }
}

__device__ __forceinline__ void store_h1(int row, int col, float v0, float v1) {
    *reinterpret_cast<float2*>(g_h1 + (size_t)row * H1S + col) = make_float2(v0, v1);
    __nv_bfloat16 h0, l0, h1b, l1b;
    bf16_split(v0, h0, l0);
    bf16_split(v1, h1b, l1b);
    __nv_bfloat16* r = g_a2bf + (size_t)row * KT2;
    *reinterpret_cast<__nv_bfloat162*>(r + col)       = __halves2bfloat162(h0, h1b);
    *reinterpret_cast<__nv_bfloat162*>(r + KH2 + col) = __halves2bfloat162(l0, l1b);
}

__global__ __launch_bounds__(256, 1) void gemm1_mma_kernel(
    const float* __restrict__ bias,
    const float* __restrict__ W1_root,
    const float* __restrict__ W1_rel)
{
    extern __shared__ __align__(1024) char sm[];
    uint32_t sb = smem_u32(sm);
    int tid  = threadIdx.x;
    int lane = tid & 31;
    int wid  = tid >> 5;
    int wm = wid & 3;
    int wn = wid >> 2;
    int bm0 = blockIdx.y * 128;
    int bn0 = blockIdx.x * 128;

    float c[2][8][4];
#pragma unroll
    for (int i = 0; i < 2; i++)
#pragma unroll
        for (int j = 0; j < 8; j++)
#pragma unroll
            for (int q = 0; q < 4; q++) c[i][j][q] = 0.f;

    int a_row  = wm * 32 + (lane & 15);
    int a_koff = (lane >> 4) * 16;
    int b_rowb = wn * 64 + ((lane >> 4) << 3) + (lane & 7);
    int b_koff = ((lane >> 3) & 1) * 16;

    g1_prefetch(sb, bm0, bn0, 0, tid);
    CP_COMMIT();

    for (int ch = 0; ch < 17; ch++) {
        if (ch < 16) {
            g1_prefetch(sb + ((ch + 1) & 1) * BUF1, bm0, bn0, (ch + 1) * 64, tid);
            CP_COMMIT();
            CP_WAIT(1);
        } else {
            CP_WAIT(0);
        }
        __syncthreads();

        uint32_t cb = sb + (ch & 1) * BUF1;
#pragma unroll
        for (int ks = 0; ks < 4; ks++) {
            int kb = ks * 32;
            uint32_t a[2][4];
#pragma unroll
            for (int mt = 0; mt < 2; mt++) {
                uint32_t off = SW128((a_row + mt * 16) * 128 + kb + a_koff);
                ldmx4(a[mt], cb + S1_A + off);
            }
            uint32_t bh[8][2], bl[8][2];
#pragma unroll
            for (int p2 = 0; p2 < 4; p2++) {
                uint32_t off = SW128((b_rowb + p2 * 16) * 128 + kb + b_koff);
                uint32_t r4[4];
                ldmx4(r4, cb + S1_BH + off);
                bh[p2 * 2][0] = r4[0]; bh[p2 * 2][1] = r4[1];
                bh[p2 * 2 + 1][0] = r4[2]; bh[p2 * 2 + 1][1] = r4[3];
                ldmx4(r4, cb + S1_BL + off);
                bl[p2 * 2][0] = r4[0]; bl[p2 * 2][1] = r4[1];
                bl[p2 * 2 + 1][0] = r4[2]; bl[p2 * 2 + 1][1] = r4[3];
            }
#pragma unroll
            for (int mt = 0; mt < 2; mt++)
#pragma unroll
                for (int nt = 0; nt < 8; nt++) {
                    mma_f16(c[mt][nt], a[mt], bh[nt]);
                    mma_f16(c[mt][nt], a[mt], bl[nt]);
                }
        }
        __syncthreads();
    }

    int g  = lane >> 2;
    int tg = lane & 3;
#pragma unroll
    for (int mt = 0; mt < 2; mt++) {
        int row0 = bm0 + wm * 32 + mt * 16 + g;
        int row1 = row0 + 8;
        float ai0 = (row0 < NN) ? g_aggidx[row0] : 0.f;
        float ai1 = (row1 < NN) ? g_aggidx[row1] : 0.f;
#pragma unroll
        for (int nt = 0; nt < 8; nt++) {
            int col = bn0 + wn * 64 + nt * 8 + tg * 2;
            float b0 = bias[col], b1 = bias[col + 1];
            float wr0 = W1_root[512 * OUT1 + col], wr1 = W1_root[512 * OUT1 + col + 1];
            float we0 = W1_rel[512 * OUT1 + col],  we1 = W1_rel[512 * OUT1 + col + 1];
            if (row0 < NN) {
                float v0 = c[mt][nt][0] + b0 + (float)row0 * wr0 + ai0 * we0;
                float v1 = c[mt][nt][1] + b1 + (float)row0 * wr1 + ai0 * we1;
                v0 = (v0 >= 0.f) ? v0 : NEG_SLOPE * v0;
                v1 = (v1 >= 0.f) ? v1 : NEG_SLOPE * v1;
                store_h1(row0, col, v0, v1);
            }
            if (row1 < NN) {
                float v2 = c[mt][nt][2] + b0 + (float)row1 * wr0 + ai1 * we0;
                float v3 = c[mt][nt][3] + b1 + (float)row1 * wr1 + ai1 * we1;
                v2 = (v2 >= 0.f) ? v2 : NEG_SLOPE * v2;
                v3 = (v3 >= 0.f) ? v3 : NEG_SLOPE * v3;
                store_h1(row1, col, v2, v3);
            }
        }
    }
}

// ---------------------------------------------------------------------------
// Aggregation 2: per-destination sum over 257 features of g_h1 (fp32),
// written split bf16 into g_a2bf cols [257..514).
// ---------------------------------------------------------------------------
__global__ void agg2_kernel() {
    int gid  = blockIdx.x * blockDim.x + threadIdx.x;
    int node = gid >> 5;
    int lane = gid & 31;
    if (node >= NN) return;

    int beg = g_offsets[node], end = g_offsets[node + 1];
    float s[9];
#pragma unroll
    for (int r = 0; r < 9; r++) s[r] = 0.f;

    for (int e = beg; e < end; e++) {
        int sr = g_csr[e];
        const float* hr = g_h1 + (size_t)sr * H1S;
#pragma unroll
        for (int r = 0; r < 9; r++) {
            int f = lane + 32 * r;
            if (f < 257) s[r] += __ldg(&hr[f]);
        }
    }
    __nv_bfloat16* row = g_a2bf + (size_t)node * KT2;
    __nv_bfloat16 hi, lo;
#pragma unroll
    for (int r = 0; r < 9; r++) {
        int f = lane + 32 * r;
        if (f < 257) {
            bf16_split(s[r], hi, lo);
            row[257 + f] = hi;
            row[KH2 + 257 + f] = lo;
        }
    }
}

// ---------------------------------------------------------------------------
// gemm2 (mma.sync bf16x3, double-buffered): h2 = leaky(A2*W2 + b2) -> g_h2.
// CTA 128x64, 8 warps (4m x 2n), warp 32x32, BK=64 (9 chunks).
// ---------------------------------------------------------------------------
#define SA2_H 0
#define SA2_L 16384
#define SB2_H 32768
#define SB2_L 40960
#define BUF2  49152
#define SMEM_G2 (2 * BUF2)

__device__ __forceinline__ void g2_prefetch(uint32_t base, int bm0, int k0, int tid) {
#pragma unroll
    for (int t = 0; t < 4; t++) {
        int item = tid + t * 256;
        int r = item >> 3, q = item & 7;
        int grow = bm0 + r;
        int ok = (grow < NN) ? 16 : 0;
        int crow = (grow < NN) ? grow : (NN - 1);
        const char* p = (const char*)(g_a2bf + (size_t)crow * KT2 + k0 + q * 8);
        uint32_t so = SW128(r * 128 + q * 16);
        cp16(base + SA2_H + so, p, ok);
        cp16(base + SA2_L + so, p + KH2 * 2, ok);
    }
#pragma unroll
    for (int t = 0; t < 2; t++) {
        int item = tid + t * 256;
        int n = item >> 3, q = item & 7;
        const char* p = (const char*)(g_w2bf + (size_t)n * KT2 + k0 + q * 8);
        uint32_t so = SW128(n * 128 + q * 16);
        cp16(base + SB2_H + so, p, 16);
        cp16(base + SB2_L + so, p + KH2 * 2, 16);
    }
}

__global__ __launch_bounds__(256, 1) void gemm2_mma_kernel(const float* __restrict__ bias) {
    extern __shared__ __align__(1024) char sm[];
    uint32_t sb = smem_u32(sm);
    int tid  = threadIdx.x;
    int lane = tid & 31;
    int wid  = tid >> 5;
    int wm = wid & 3;
    int wn = wid >> 2;
    int bm0 = blockIdx.x * 128;

    float c[2][4][4];
#pragma unroll
    for (int i = 0; i < 2; i++)
#pragma unroll
        for (int j = 0; j < 4; j++)
#pragma unroll
            for (int q = 0; q < 4; q++) c[i][j][q] = 0.f;

    int a_row  = wm * 32 + (lane & 15);
    int a_koff = (lane >> 4) * 16;
    int b_rowb = wn * 32 + ((lane >> 4) << 3) + (lane & 7);
    int b_koff = ((lane >> 3) & 1) * 16;

    g2_prefetch(sb, bm0, 0, tid);
    CP_COMMIT();

    for (int ch = 0; ch < 9; ch++) {
        if (ch < 8) {
            g2_prefetch(sb + ((ch + 1) & 1) * BUF2, bm0, (ch + 1) * 64, tid);
            CP_COMMIT();
            CP_WAIT(1);
        } else {
            CP_WAIT(0);
        }
        __syncthreads();

        uint32_t cb = sb + (ch & 1) * BUF2;
#pragma unroll
        for (int ks = 0; ks < 4; ks++) {
            int kb = ks * 32;
            uint32_t ah[2][4], al[2][4];
#pragma unroll
            for (int mt = 0; mt < 2; mt++) {
                uint32_t off = SW128((a_row + mt * 16) * 128 + kb + a_koff);
                ldmx4(ah[mt], cb + SA2_H + off);
                ldmx4(al[mt], cb + SA2_L + off);
            }
            uint32_t bh[4][2], bl[4][2];
#pragma unroll
            for (int p2 = 0; p2 < 2; p2++) {
                uint32_t off = SW128((b_rowb + p2 * 16) * 128 + kb + b_koff);
                uint32_t r4[4];
                ldmx4(r4, cb + SB2_H + off);
                bh[p2 * 2][0] = r4[0]; bh[p2 * 2][1] = r4[1];
                bh[p2 * 2 + 1][0] = r4[2]; bh[p2 * 2 + 1][1] = r4[3];
                ldmx4(r4, cb + SB2_L + off);
                bl[p2 * 2][0] = r4[0]; bl[p2 * 2][1] = r4[1];
                bl[p2 * 2 + 1][0] = r4[2]; bl[p2 * 2 + 1][1] = r4[3];
            }
#pragma unroll
            for (int mt = 0; mt < 2; mt++)
#pragma unroll
                for (int nt = 0; nt < 4; nt++) {
                    mma_bf16(c[mt][nt], ah[mt], bh[nt]);
                    mma_bf16(c[mt][nt], al[mt], bh[nt]);
                    mma_bf16(c[mt][nt], ah[mt], bl[nt]);
                }
        }
        __syncthreads();
    }

    int g  = lane >> 2;
    int tg = lane & 3;
#pragma unroll
    for (int mt = 0; mt < 2; mt++) {
        int row0 = bm0 + wm * 32 + mt * 16 + g;
        int row1 = row0 + 8;
#pragma unroll
        for (int nt = 0; nt < 4; nt++) {
            int col = wn * 32 + nt * 8 + tg * 2;
            float b0 = bias[col], b1 = bias[col + 1];
            if (row0 < NN) {
                float v0 = c[mt][nt][0] + b0;  v0 = (v0 >= 0.f) ? v0 : NEG_SLOPE * v0;
                float v1 = c[mt][nt][1] + b1;  v1 = (v1 >= 0.f) ? v1 : NEG_SLOPE * v1;
                *reinterpret_cast<float2*>(g_h2 + (size_t)row0 * OUT2 + col) =
                    make_float2(v0, v1);
            }
            if (row1 < NN) {
                float v2 = c[mt][nt][2] + b0;  v2 = (v2 >= 0.f) ? v2 : NEG_SLOPE * v2;
                float v3 = c[mt][nt][3] + b1;  v3 = (v3 >= 0.f) ? v3 : NEG_SLOPE * v3;
                *reinterpret_cast<float2*>(g_h2 + (size_t)row1 * OUT2 + col) =
                    make_float2(v2, v3);
            }
        }
    }
}

// ---------------------------------------------------------------------------
// Output heads
// ---------------------------------------------------------------------------
__global__ void heads_kernel(const float* __restrict__ Wp, const float* __restrict__ bp,
                             const float* __restrict__ Wr, const float* __restrict__ br,
                             float* __restrict__ out) {
    int gid  = blockIdx.x * blockDim.x + threadIdx.x;
    int node = gid >> 5;
    int lane = gid & 31;
    if (node >= NN) return;

    float v0 = g_h2[(size_t)node * OUT2 + lane];
    float v1 = g_h2[(size_t)node * OUT2 + 32 + lane];

    float res[7];
#pragma unroll
    for (int o = 0; o < 7; o++) {
        float w0, w1, wlast, bb;
        if (o < 3) {
            w0 = Wp[lane * 3 + o];  w1 = Wp[(lane + 32) * 3 + o];
            wlast = Wp[64 * 3 + o]; bb = bp[o];
        } else {
            int oo = o - 3;
            w0 = Wr[lane * 4 + oo]; w1 = Wr[(lane + 32) * 4 + oo];
            wlast = Wr[64 * 4 + oo]; bb = br[oo];
        }
        float p = v0 * w0 + v1 * w1;
#pragma unroll
        for (int sft = 16; sft > 0; sft >>= 1)
            p += __shfl_down_sync(0xffffffffu, p, sft);
        res[o] = p + (float)node * wlast + bb;
    }
    if (lane == 0) {
        float r0 = res[3], r1 = res[4], r2 = res[5], r3 = res[6];
        float n = sqrtf(r0 * r0 + r1 * r1 + r2 * r2 + r3 * r3);
        n = fmaxf(n, 1e-12f);
        float* o = out + (size_t)node * 7;
        o[0] = res[0]; o[1] = res[1]; o[2] = res[2];
        o[3] = r0 / n; o[4] = r1 / n; o[5] = r2 / n; o[6] = r3 / n;
    }
}

// ---------------------------------------------------------------------------
// Launch sequence
// ---------------------------------------------------------------------------
extern "C" void kernel_launch(void* const* d_in, const int* in_sizes, int n_in,
                              void* d_out, int out_size) {
    const float* x       = (const float*)d_in[0];
    const float* W1_rel  = (const float*)d_in[1];
    const float* b1      = (const float*)d_in[2];
    const float* W1_root = (const float*)d_in[3];
    const float* W2_rel  = (const float*)d_in[4];
    const float* b2      = (const float*)d_in[5];
    const float* W2_root = (const float*)d_in[6];
    const float* Wp      = (const float*)d_in[7];
    const float* bp      = (const float*)d_in[8];
    const float* Wr      = (const float*)d_in[9];
    const float* br      = (const float*)d_in[10];
    const void*  ei      = d_in[11];
    float* out           = (float*)d_out;

    cudaFuncSetAttribute(gemm1_mma_kernel,
                         cudaFuncAttributeMaxDynamicSharedMemorySize, SMEM_G1);
    cudaFuncSetAttribute(gemm2_mma_kernel,
                         cudaFuncAttributeMaxDynamicSharedMemorySize, SMEM_G2);

    // PQ precompute (independent of CSR)
    pq_kernel<<<(NN * F0 + 255) / 256, 256>>>(x);

    // CSR build
    detect_kernel<<<1, 256>>>((const int*)ei);
    zero_kernel<<<(NN + 255) / 256, 256>>>();
    hist_kernel<<<(EE + 255) / 256, 256>>>(ei);
    scan1_kernel<<<SCAN_B, 256>>>();
    scan2_kernel<<<1, 256>>>();
    scan3_kernel<<<SCAN_B, 256>>>();
    scatter_kernel<<<(EE + 255) / 256, 256>>>(ei);

    // prep
    wsplit1_kernel<<<(OUT1 * KH + 255) / 256, 256>>>(W1_root, W1_rel);
    wsplit2_kernel<<<(OUT2 * KH2 + 255) / 256, 256>>>(W2_root, W2_rel);
    node_prep_kernel<<<(NN + 255) / 256, 256>>>();

    // layer 1
    agg1_kernel<<<(NN * 32 + 255) / 256, 256>>>(x);
    {
        dim3 grid(OUT1 / 128, (NN + 127) / 128);
        gemm1_mma_kernel<<<grid, 256, SMEM_G1>>>(b1, W1_root, W1_rel);
    }

    // layer 2
    agg2_kernel<<<(NN * 32 + 255) / 256, 256>>>();
    gemm2_mma_kernel<<<(NN + 127) / 128, 256, SMEM_G2>>>(b2);

    // heads
    heads_kernel<<<(NN * 32 + 255) / 256, 256>>>(Wp, bp, Wr, br, out);
}

// round 14
// speedup vs baseline: 1.2457x; 1.2457x over previous
#include <cuda_runtime.h>
#include <cuda_bf16.h>
#include <cuda_fp16.h>
#include <math.h>
#include <cstdint>

// ---------------------------------------------------------------------------
// Problem constants
// ---------------------------------------------------------------------------
#define NN   50000
#define EE   200000
#define F0   512

// Layer 1: A = [x(512)|0|agg1(512)|0|pad] -> KH=1088 (idx cols zeroed, handled
// exactly in epilogue). A stored as plain fp16; W split fp16 hi/lo.
#define KH   1088
#define OUT1 256

// Layer 2: A2 = [h1(256)|idx(1)|agg2(257)|pad(62)] -> KH2=576, split bf16 x3.
#define KH2  576
#define KT2  (2*KH2)
#define OUT2 64

// fp32 h1' buffer for agg2 gather: [h1(256)|idx(1)] stride 260
#define H1S  260

#define NEG_SLOPE 0.01f

// ---------------------------------------------------------------------------
// Scratch (static device globals)
// ---------------------------------------------------------------------------
__device__ __align__(256) __half g_a1h[(size_t)NN * KH];            // ~109 MB
__device__ __align__(256) __half g_w1h[(size_t)OUT1 * 2 * KH];      // hi at k, lo at KH+k
__device__ __align__(256) __nv_bfloat16 g_a2bf[(size_t)NN * KT2];   // ~115 MB
__device__ __align__(256) __nv_bfloat16 g_w2bf[(size_t)OUT2 * KT2];
__device__ __align__(256) float g_h1[(size_t)NN * H1S];             // ~52 MB
__device__ __align__(256) float g_h2[(size_t)NN * OUT2];            // ~13 MB
__device__ __align__(256) float g_aggidx[NN];
__device__ int g_counts[NN];
__device__ int g_cursor[NN];
__device__ int g_offsets[NN + 1];
__device__ int g_csr[EE];
__device__ int g_blocksum[256];
__device__ int g_blockoff[256];
__device__ int g_idx_is32;

// ---------------------------------------------------------------------------
// Helpers
// ---------------------------------------------------------------------------
__device__ __forceinline__ uint32_t smem_u32(const void* p) {
    uint32_t a;
    asm("{ .reg .u64 t; cvta.to.shared.u64 t, %1; cvt.u32.u64 %0, t; }" : "=r"(a) : "l"(p));
    return a;
}

#define SW128(off) ((off) ^ (((off) >> 3) & 0x70))

__device__ __forceinline__ void ldmx4(uint32_t r[4], uint32_t addr) {
    asm volatile("ldmatrix.sync.aligned.m8n8.x4.shared.b16 {%0,%1,%2,%3}, [%4];"
        : "=r"(r[0]), "=r"(r[1]), "=r"(r[2]), "=r"(r[3]) : "r"(addr));
}

__device__ __forceinline__ void mma_bf16(float c[4], const uint32_t a[4], const uint32_t b[2]) {
    asm volatile("mma.sync.aligned.m16n8k16.row.col.f32.bf16.bf16.f32 "
        "{%0,%1,%2,%3}, {%4,%5,%6,%7}, {%8,%9}, {%0,%1,%2,%3};"
        : "+f"(c[0]), "+f"(c[1]), "+f"(c[2]), "+f"(c[3])
        : "r"(a[0]), "r"(a[1]), "r"(a[2]), "r"(a[3]), "r"(b[0]), "r"(b[1]));
}

__device__ __forceinline__ void mma_f16(float c[4], const uint32_t a[4], const uint32_t b[2]) {
    asm volatile("mma.sync.aligned.m16n8k16.row.col.f32.f16.f16.f32 "
        "{%0,%1,%2,%3}, {%4,%5,%6,%7}, {%8,%9}, {%0,%1,%2,%3};"
        : "+f"(c[0]), "+f"(c[1]), "+f"(c[2]), "+f"(c[3])
        : "r"(a[0]), "r"(a[1]), "r"(a[2]), "r"(a[3]), "r"(b[0]), "r"(b[1]));
}

__device__ __forceinline__ void cp16(uint32_t saddr, const void* gaddr, int nbytes) {
    asm volatile("cp.async.cg.shared.global [%0], [%1], 16, %2;"
        :: "r"(saddr), "l"(gaddr), "r"(nbytes));
}
#define CP_COMMIT() asm volatile("cp.async.commit_group;" ::: "memory")
#define CP_WAIT(n)  asm volatile("cp.async.wait_group %0;" :: "n"(n) : "memory")

__device__ __forceinline__ void bf16_split(float v, __nv_bfloat16& hi, __nv_bfloat16& lo) {
    hi = __float2bfloat16(v);
    lo = __float2bfloat16(v - __bfloat162float(hi));
}

__device__ __forceinline__ void f16_split(float v, __half& hi, __half& lo) {
    hi = __float2half(v);
    lo = __float2half(v - __half2float(hi));
}

// softmax-accumulate 4 features (exp cannot overflow: x ~ N(0,1))
__device__ __forceinline__ void accum4(float* d, float* num, float4 v) {
    float e0 = __expf(v.x); d[0] += e0; num[0] = fmaf(e0, v.x, num[0]);
    float e1 = __expf(v.y); d[1] += e1; num[1] = fmaf(e1, v.y, num[1]);
    float e2 = __expf(v.z); d[2] += e2; num[2] = fmaf(e2, v.z, num[2]);
    float e3 = __expf(v.w); d[3] += e3; num[3] = fmaf(e3, v.w, num[3]);
}

// online-max softmax update (index feature, values up to 5e4)
__device__ __forceinline__ void upd_idx(float& m, float& d, float& n, float v) {
    float nm = fmaxf(m, v);
    float sc = __expf(m - nm);
    float ev = __expf(v - nm);
    d = d * sc + ev;
    n = n * sc + ev * v;
    m = nm;
}

// inclusive block scan over 256 threads; warp_part must be __shared__ int[8]
__device__ __forceinline__ int block_incl_scan_256(int v, int* warp_part) {
    int lane = threadIdx.x & 31, w = threadIdx.x >> 5;
    int x = v;
#pragma unroll
    for (int o = 1; o < 32; o <<= 1) {
        int u = __shfl_up_sync(0xffffffffu, x, o);
        if (lane >= o) x += u;
    }
    if (lane == 31) warp_part[w] = x;
    __syncthreads();
    if (w == 0) {
        int y = (lane < 8) ? warp_part[lane] : 0;
#pragma unroll
        for (int o = 1; o < 8; o <<= 1) {
            int u = __shfl_up_sync(0xffffffffu, y, o);
            if (lane >= o) y += u;
        }
        if (lane < 8) warp_part[lane] = y;
    }
    __syncthreads();
    return x + ((w > 0) ? warp_part[w - 1] : 0);
}

// ---------------------------------------------------------------------------
// edge_index dtype detection (int64 vs int32-demoted)
// ---------------------------------------------------------------------------
__global__ void detect_kernel(const int* ei_words) {
    __shared__ int acc;
    if (threadIdx.x == 0) acc = 0;
    __syncthreads();
    int v = ei_words[2 * threadIdx.x + 1];
    if (v != 0) atomicOr(&acc, 1);
    __syncthreads();
    if (threadIdx.x == 0) g_idx_is32 = acc;
}

__device__ __forceinline__ int edge_val(const void* ei, int idx) {
    if (g_idx_is32) return ((const int*)ei)[idx];
    return (int)((const long long*)ei)[idx];
}

// ---------------------------------------------------------------------------
// CSR build (by destination)
// ---------------------------------------------------------------------------
__global__ void zero_kernel() {
    int i = blockIdx.x * blockDim.x + threadIdx.x;
    if (i < NN) { g_counts[i] = 0; g_cursor[i] = 0; }
}

__global__ void hist_kernel(const void* ei) {
    int e = blockIdx.x * blockDim.x + threadIdx.x;
    if (e >= EE) return;
    int d = edge_val(ei, EE + e);
    if ((unsigned)d < NN) atomicAdd(&g_counts[d], 1);
}

#define SCAN_B 196   // ceil(50000/256)

__global__ void scan1_kernel() {
    __shared__ int wp[8];
    int i = blockIdx.x * 256 + threadIdx.x;
    int v = (i < NN) ? g_counts[i] : 0;
    int incl = block_incl_scan_256(v, wp);
    if (threadIdx.x == 255) g_blocksum[blockIdx.x] = incl;
}

__global__ void scan2_kernel() {
    __shared__ int wp[8];
    int t = threadIdx.x;
    int v = (t < SCAN_B) ? g_blocksum[t] : 0;
    int incl = block_incl_scan_256(v, wp);
    if (t < SCAN_B) g_blockoff[t] = incl - v;
    if (t == 255) g_offsets[NN] = incl;
}

__global__ void scan3_kernel() {
    __shared__ int wp[8];
    int i = blockIdx.x * 256 + threadIdx.x;
    int v = (i < NN) ? g_counts[i] : 0;
    int incl = block_incl_scan_256(v, wp);
    if (i < NN) g_offsets[i] = incl - v + g_blockoff[blockIdx.x];
}

__global__ void scatter_kernel(const void* ei) {
    int e = blockIdx.x * blockDim.x + threadIdx.x;
    if (e >= EE) return;
    int s = edge_val(ei, e);
    int d = edge_val(ei, EE + e);
    if ((unsigned)d >= NN) return;
    int pos = g_offsets[d] + atomicAdd(&g_cursor[d], 1);
    g_csr[pos] = s;
}

// ---------------------------------------------------------------------------
// Weight prep
// ---------------------------------------------------------------------------
__global__ void wsplit1_kernel(const float* __restrict__ W1_root,
                               const float* __restrict__ W1_rel) {
    int idx = blockIdx.x * blockDim.x + threadIdx.x;
    if (idx >= OUT1 * KH) return;
    int n = idx / KH, k = idx - n * KH;
    float w = 0.f;
    if (k < 513)       w = W1_root[k * OUT1 + n];
    else if (k < 1026) w = W1_rel[(k - 513) * OUT1 + n];
    __half hi, lo;
    f16_split(w, hi, lo);
    g_w1h[(size_t)n * (2 * KH) + k]      = hi;
    g_w1h[(size_t)n * (2 * KH) + KH + k] = lo;
}

__global__ void wsplit2_kernel(const float* __restrict__ W2_root,
                               const float* __restrict__ W2_rel) {
    int idx = blockIdx.x * blockDim.x + threadIdx.x;
    if (idx >= OUT2 * KH2) return;
    int n = idx / KH2, k = idx - n * KH2;
    float w = 0.f;
    if (k < 257)      w = W2_root[k * OUT2 + n];
    else if (k < 514) w = W2_rel[(k - 257) * OUT2 + n];
    __nv_bfloat16 hi, lo;
    bf16_split(w, hi, lo);
    g_w2bf[(size_t)n * KT2 + k]       = hi;
    g_w2bf[(size_t)n * KT2 + KH2 + k] = lo;
}

__global__ void node_prep_kernel() {
    int i = blockIdx.x * blockDim.x + threadIdx.x;
    if (i >= NN) return;
    g_h1[(size_t)i * H1S + 256] = (float)i;
    __nv_bfloat16 hi, lo;
    bf16_split((float)i, hi, lo);
    __nv_bfloat16* r = g_a2bf + (size_t)i * KT2;
    r[256] = hi; r[KH2 + 256] = lo;
    __nv_bfloat16 z = __float2bfloat16(0.f);
#pragma unroll
    for (int p = 514; p < KH2; p++) { r[p] = z; r[KH2 + p] = z; }
}

// ---------------------------------------------------------------------------
// Aggregation 1: per-destination softmax aggregation over 513 features.
// float4 gather (4 x LDG.128 per edge per lane) + 2-edge unroll -> 8
// independent 16B loads in flight; exps are hidden under gather latency.
// Lane owns features f = t*128 + lane*4 + j (t<4, j<4).
// Emits fp16 A1 row [x|0|agg|0|pad] and fp32 g_aggidx.
// ---------------------------------------------------------------------------
__global__ void agg1_kernel(const float* __restrict__ x) {
    int gid  = blockIdx.x * blockDim.x + threadIdx.x;
    int node = gid >> 5;
    int lane = gid & 31;
    if (node >= NN) return;

    int beg = g_offsets[node], end = g_offsets[node + 1];

    float d[16], num[16];
#pragma unroll
    for (int r = 0; r < 16; r++) { d[r] = 0.f; num[r] = 0.f; }
    float mi = -1e30f, di = 0.f, numi = 0.f;

    int e = beg;
    for (; e + 1 < end; e += 2) {
        int s0 = g_csr[e], s1 = g_csr[e + 1];
        const float4* p0 = reinterpret_cast<const float4*>(x + (size_t)s0 * F0) + lane;
        const float4* p1 = reinterpret_cast<const float4*>(x + (size_t)s1 * F0) + lane;
        float4 a0 = __ldg(p0),      a1 = __ldg(p0 + 32),
               a2 = __ldg(p0 + 64), a3 = __ldg(p0 + 96);
        float4 b0 = __ldg(p1),      b1 = __ldg(p1 + 32),
               b2 = __ldg(p1 + 64), b3 = __ldg(p1 + 96);
        accum4(d + 0,  num + 0,  a0); accum4(d + 4,  num + 4,  a1);
        accum4(d + 8,  num + 8,  a2); accum4(d + 12, num + 12, a3);
        accum4(d + 0,  num + 0,  b0); accum4(d + 4,  num + 4,  b1);
        accum4(d + 8,  num + 8,  b2); accum4(d + 12, num + 12, b3);
        if (lane == 0) {
            upd_idx(mi, di, numi, (float)s0);
            upd_idx(mi, di, numi, (float)s1);
        }
    }
    if (e < end) {
        int s0 = g_csr[e];
        const float4* p0 = reinterpret_cast<const float4*>(x + (size_t)s0 * F0) + lane;
        float4 a0 = __ldg(p0),      a1 = __ldg(p0 + 32),
               a2 = __ldg(p0 + 64), a3 = __ldg(p0 + 96);
        accum4(d + 0,  num + 0,  a0); accum4(d + 4,  num + 4,  a1);
        accum4(d + 8,  num + 8,  a2); accum4(d + 12, num + 12, a3);
        if (lane == 0) upd_idx(mi, di, numi, (float)s0);
    }

    __half* row = g_a1h + (size_t)node * KH;
    const float4* xi = reinterpret_cast<const float4*>(x + (size_t)node * F0) + lane;
#pragma unroll
    for (int t = 0; t < 4; t++) {
        float4 v = __ldg(xi + t * 32);
        // byte offset (t*128 + lane*4)*2 -> 8B aligned
        *reinterpret_cast<__half2*>(row + t * 128 + lane * 4)     = __floats2half2_rn(v.x, v.y);
        *reinterpret_cast<__half2*>(row + t * 128 + lane * 4 + 2) = __floats2half2_rn(v.z, v.w);
    }
    bool nonempty = (end > beg);
#pragma unroll
    for (int t = 0; t < 4; t++)
#pragma unroll
        for (int j = 0; j < 4; j++) {
            int f = t * 128 + lane * 4 + j;
            float o = nonempty ? (num[t * 4 + j] / fmaxf(d[t * 4 + j], 1e-16f)) : 0.f;
            row[513 + f] = __float2half(o);
        }
    if (lane == 0) {
        float o = nonempty ? (numi / fmaxf(di, 1e-16f)) : 0.f;
        g_aggidx[node] = o;
        row[512]  = __float2half(0.f);
        row[1025] = __float2half(0.f);
    }
    __half z = __float2half(0.f);
    for (int f = 1026 + lane; f < KH; f += 32) row[f] = z;
}

// ---------------------------------------------------------------------------
// gemm1 (mma.sync fp16x2, double-buffered cp.async):
// h1 = leaky(A1*W1 + b1 + node*W_root[512] + aggidx*W_rel[512]).
// A plain fp16, B split hi/lo; 2 MMA passes: A*Bh + A*Bl.
// CTA 128x128, 8 warps (4m x 2n), BK=64 (17 chunks).
// ---------------------------------------------------------------------------
#define S1_A  0
#define S1_BH 16384
#define S1_BL 32768
#define BUF1  49152
#define SMEM_G1 (2 * BUF1)

__device__ __forceinline__ void g1_prefetch(uint32_t base, int bm0, int bn0,
                                            int k0, int tid) {
#pragma unroll
    for (int t = 0; t < 4; t++) {
        int item = tid + t * 256;
        int r = item >> 3, q = item & 7;
        int grow = bm0 + r;
        int ok = (grow < NN) ? 16 : 0;
        int crow = (grow < NN) ? grow : (NN - 1);
        const char* p = (const char*)(g_a1h + (size_t)crow * KH + k0 + q * 8);
        cp16(base + S1_A + SW128(r * 128 + q * 16), p, ok);
    }
#pragma unroll
    for (int t = 0; t < 4; t++) {
        int item = tid + t * 256;
        int n = item >> 3, q = item & 7;
        const char* p = (const char*)(g_w1h + (size_t)(bn0 + n) * (2 * KH) + k0 + q * 8);
        uint32_t so = SW128(n * 128 + q * 16);
        cp16(base + S1_BH + so, p, 16);
        cp16(base + S1_BL + so, p + KH * 2, 16);
    }
}

__device__ __forceinline__ void store_h1(int row, int col, float v0, float v1) {
    *reinterpret_cast<float2*>(g_h1 + (size_t)row * H1S + col) = make_float2(v0, v1);
    __nv_bfloat16 h0, l0, h1b, l1b;
    bf16_split(v0, h0, l0);
    bf16_split(v1, h1b, l1b);
    __nv_bfloat16* r = g_a2bf + (size_t)row * KT2;
    *reinterpret_cast<__nv_bfloat162*>(r + col)       = __halves2bfloat162(h0, h1b);
    *reinterpret_cast<__nv_bfloat162*>(r + KH2 + col) = __halves2bfloat162(l0, l1b);
}

__global__ __launch_bounds__(256, 1) void gemm1_mma_kernel(
    const float* __restrict__ bias,
    const float* __restrict__ W1_root,
    const float* __restrict__ W1_rel)
{
    extern __shared__ __align__(1024) char sm[];
    uint32_t sb = smem_u32(sm);
    int tid  = threadIdx.x;
    int lane = tid & 31;
    int wid  = tid >> 5;
    int wm = wid & 3;
    int wn = wid >> 2;
    int bm0 = blockIdx.y * 128;
    int bn0 = blockIdx.x * 128;

    float c[2][8][4];
#pragma unroll
    for (int i = 0; i < 2; i++)
#pragma unroll
        for (int j = 0; j < 8; j++)
#pragma unroll
            for (int q = 0; q < 4; q++) c[i][j][q] = 0.f;

    int a_row  = wm * 32 + (lane & 15);
    int a_koff = (lane >> 4) * 16;
    int b_rowb = wn * 64 + ((lane >> 4) << 3) + (lane & 7);
    int b_koff = ((lane >> 3) & 1) * 16;

    g1_prefetch(sb, bm0, bn0, 0, tid);
    CP_COMMIT();

    for (int ch = 0; ch < 17; ch++) {
        if (ch < 16) {
            g1_prefetch(sb + ((ch + 1) & 1) * BUF1, bm0, bn0, (ch + 1) * 64, tid);
            CP_COMMIT();
            CP_WAIT(1);
        } else {
            CP_WAIT(0);
        }
        __syncthreads();

        uint32_t cb = sb + (ch & 1) * BUF1;
#pragma unroll
        for (int ks = 0; ks < 4; ks++) {
            int kb = ks * 32;
            uint32_t a[2][4];
#pragma unroll
            for (int mt = 0; mt < 2; mt++) {
                uint32_t off = SW128((a_row + mt * 16) * 128 + kb + a_koff);
                ldmx4(a[mt], cb + S1_A + off);
            }
            uint32_t bh[8][2], bl[8][2];
#pragma unroll
            for (int p2 = 0; p2 < 4; p2++) {
                uint32_t off = SW128((b_rowb + p2 * 16) * 128 + kb + b_koff);
                uint32_t r4[4];
                ldmx4(r4, cb + S1_BH + off);
                bh[p2 * 2][0] = r4[0]; bh[p2 * 2][1] = r4[1];
                bh[p2 * 2 + 1][0] = r4[2]; bh[p2 * 2 + 1][1] = r4[3];
                ldmx4(r4, cb + S1_BL + off);
                bl[p2 * 2][0] = r4[0]; bl[p2 * 2][1] = r4[1];
                bl[p2 * 2 + 1][0] = r4[2]; bl[p2 * 2 + 1][1] = r4[3];
            }
#pragma unroll
            for (int mt = 0; mt < 2; mt++)
#pragma unroll
                for (int nt = 0; nt < 8; nt++) {
                    mma_f16(c[mt][nt], a[mt], bh[nt]);
                    mma_f16(c[mt][nt], a[mt], bl[nt]);
                }
        }
        __syncthreads();
    }

    int g  = lane >> 2;
    int tg = lane & 3;
#pragma unroll
    for (int mt = 0; mt < 2; mt++) {
        int row0 = bm0 + wm * 32 + mt * 16 + g;
        int row1 = row0 + 8;
        float ai0 = (row0 < NN) ? g_aggidx[row0] : 0.f;
        float ai1 = (row1 < NN) ? g_aggidx[row1] : 0.f;
#pragma unroll
        for (int nt = 0; nt < 8; nt++) {
            int col = bn0 + wn * 64 + nt * 8 + tg * 2;
            float b0 = bias[col], b1 = bias[col + 1];
            float wr0 = W1_root[512 * OUT1 + col], wr1 = W1_root[512 * OUT1 + col + 1];
            float we0 = W1_rel[512 * OUT1 + col],  we1 = W1_rel[512 * OUT1 + col + 1];
            if (row0 < NN) {
                float v0 = c[mt][nt][0] + b0 + (float)row0 * wr0 + ai0 * we0;
                float v1 = c[mt][nt][1] + b1 + (float)row0 * wr1 + ai0 * we1;
                v0 = (v0 >= 0.f) ? v0 : NEG_SLOPE * v0;
                v1 = (v1 >= 0.f) ? v1 : NEG_SLOPE * v1;
                store_h1(row0, col, v0, v1);
            }
            if (row1 < NN) {
                float v2 = c[mt][nt][2] + b0 + (float)row1 * wr0 + ai1 * we0;
                float v3 = c[mt][nt][3] + b1 + (float)row1 * wr1 + ai1 * we1;
                v2 = (v2 >= 0.f) ? v2 : NEG_SLOPE * v2;
                v3 = (v3 >= 0.f) ? v3 : NEG_SLOPE * v3;
                store_h1(row1, col, v2, v3);
            }
        }
    }
}

// ---------------------------------------------------------------------------
// Aggregation 2: per-destination sum over 257 features of g_h1 (fp32).
// float4 gather (2 x LDG.128 per edge per lane) + 2-edge unroll.
// Index column needs no load: h1[s][256] == (float)s.
// Lane owns features f = t*128 + lane*4 + j (t<2, j<4).
// Written split bf16 into g_a2bf cols [257..514).
// ---------------------------------------------------------------------------
__global__ void agg2_kernel() {
    int gid  = blockIdx.x * blockDim.x + threadIdx.x;
    int node = gid >> 5;
    int lane = gid & 31;
    if (node >= NN) return;

    int beg = g_offsets[node], end = g_offsets[node + 1];
    float s[8];
#pragma unroll
    for (int r = 0; r < 8; r++) s[r] = 0.f;
    float sidx = 0.f;

    int e = beg;
    for (; e + 1 < end; e += 2) {
        int s0 = g_csr[e], s1 = g_csr[e + 1];
        const float4* p0 = reinterpret_cast<const float4*>(g_h1 + (size_t)s0 * H1S) + lane;
        const float4* p1 = reinterpret_cast<const float4*>(g_h1 + (size_t)s1 * H1S) + lane;
        float4 a0 = __ldg(p0), a1 = __ldg(p0 + 32);
        float4 b0 = __ldg(p1), b1 = __ldg(p1 + 32);
        s[0] += a0.x + b0.x; s[1] += a0.y + b0.y;
        s[2] += a0.z + b0.z; s[3] += a0.w + b0.w;
        s[4] += a1.x + b1.x; s[5] += a1.y + b1.y;
        s[6] += a1.z + b1.z; s[7] += a1.w + b1.w;
        sidx += (float)s0 + (float)s1;
    }
    if (e < end) {
        int s0 = g_csr[e];
        const float4* p0 = reinterpret_cast<const float4*>(g_h1 + (size_t)s0 * H1S) + lane;
        float4 a0 = __ldg(p0), a1 = __ldg(p0 + 32);
        s[0] += a0.x; s[1] += a0.y; s[2] += a0.z; s[3] += a0.w;
        s[4] += a1.x; s[5] += a1.y; s[6] += a1.z; s[7] += a1.w;
        sidx += (float)s0;
    }

    __nv_bfloat16* row = g_a2bf + (size_t)node * KT2;
    __nv_bfloat16 hi, lo;
#pragma unroll
    for (int t = 0; t < 2; t++)
#pragma unroll
        for (int j = 0; j < 4; j++) {
            int f = t * 128 + lane * 4 + j;
            bf16_split(s[t * 4 + j], hi, lo);
            row[257 + f] = hi;
            row[KH2 + 257 + f] = lo;
        }
    if (lane == 0) {
        bf16_split(sidx, hi, lo);
        row[257 + 256] = hi;
        row[KH2 + 257 + 256] = lo;
    }
}

// ---------------------------------------------------------------------------
// gemm2 (mma.sync bf16x3, double-buffered): h2 = leaky(A2*W2 + b2) -> g_h2.
// CTA 128x64, 8 warps (4m x 2n), warp 32x32, BK=64 (9 chunks).
// ---------------------------------------------------------------------------
#define SA2_H 0
#define SA2_L 16384
#define SB2_H 32768
#define SB2_L 40960
#define BUF2  49152
#define SMEM_G2 (2 * BUF2)

__device__ __forceinline__ void g2_prefetch(uint32_t base, int bm0, int k0, int tid) {
#pragma unroll
    for (int t = 0; t < 4; t++) {
        int item = tid + t * 256;
        int r = item >> 3, q = item & 7;
        int grow = bm0 + r;
        int ok = (grow < NN) ? 16 : 0;
        int crow = (grow < NN) ? grow : (NN - 1);
        const char* p = (const char*)(g_a2bf + (size_t)crow * KT2 + k0 + q * 8);
        uint32_t so = SW128(r * 128 + q * 16);
        cp16(base + SA2_H + so, p, ok);
        cp16(base + SA2_L + so, p + KH2 * 2, ok);
    }
#pragma unroll
    for (int t = 0; t < 2; t++) {
        int item = tid + t * 256;
        int n = item >> 3, q = item & 7;
        const char* p = (const char*)(g_w2bf + (size_t)n * KT2 + k0 + q * 8);
        uint32_t so = SW128(n * 128 + q * 16);
        cp16(base + SB2_H + so, p, 16);
        cp16(base + SB2_L + so, p + KH2 * 2, 16);
    }
}

__global__ __launch_bounds__(256, 1) void gemm2_mma_kernel(const float* __restrict__ bias) {
    extern __shared__ __align__(1024) char sm[];
    uint32_t sb = smem_u32(sm);
    int tid  = threadIdx.x;
    int lane = tid & 31;
    int wid  = tid >> 5;
    int wm = wid & 3;
    int wn = wid >> 2;
    int bm0 = blockIdx.x * 128;

    float c[2][4][4];
#pragma unroll
    for (int i = 0; i < 2; i++)
#pragma unroll
        for (int j = 0; j < 4; j++)
#pragma unroll
            for (int q = 0; q < 4; q++) c[i][j][q] = 0.f;

    int a_row  = wm * 32 + (lane & 15);
    int a_koff = (lane >> 4) * 16;
    int b_rowb = wn * 32 + ((lane >> 4) << 3) + (lane & 7);
    int b_koff = ((lane >> 3) & 1) * 16;

    g2_prefetch(sb, bm0, 0, tid);
    CP_COMMIT();

    for (int ch = 0; ch < 9; ch++) {
        if (ch < 8) {
            g2_prefetch(sb + ((ch + 1) & 1) * BUF2, bm0, (ch + 1) * 64, tid);
            CP_COMMIT();
            CP_WAIT(1);
        } else {
            CP_WAIT(0);
        }
        __syncthreads();

        uint32_t cb = sb + (ch & 1) * BUF2;
#pragma unroll
        for (int ks = 0; ks < 4; ks++) {
            int kb = ks * 32;
            uint32_t ah[2][4], al[2][4];
#pragma unroll
            for (int mt = 0; mt < 2; mt++) {
                uint32_t off = SW128((a_row + mt * 16) * 128 + kb + a_koff);
                ldmx4(ah[mt], cb + SA2_H + off);
                ldmx4(al[mt], cb + SA2_L + off);
            }
            uint32_t bh[4][2], bl[4][2];
#pragma unroll
            for (int p2 = 0; p2 < 2; p2++) {
                uint32_t off = SW128((b_rowb + p2 * 16) * 128 + kb + b_koff);
                uint32_t r4[4];
                ldmx4(r4, cb + SB2_H + off);
                bh[p2 * 2][0] = r4[0]; bh[p2 * 2][1] = r4[1];
                bh[p2 * 2 + 1][0] = r4[2]; bh[p2 * 2 + 1][1] = r4[3];
                ldmx4(r4, cb + SB2_L + off);
                bl[p2 * 2][0] = r4[0]; bl[p2 * 2][1] = r4[1];
                bl[p2 * 2 + 1][0] = r4[2]; bl[p2 * 2 + 1][1] = r4[3];
            }
#pragma unroll
            for (int mt = 0; mt < 2; mt++)
#pragma unroll
                for (int nt = 0; nt < 4; nt++) {
                    mma_bf16(c[mt][nt], ah[mt], bh[nt]);
                    mma_bf16(c[mt][nt], al[mt], bh[nt]);
                    mma_bf16(c[mt][nt], ah[mt], bl[nt]);
                }
        }
        __syncthreads();
    }

    int g  = lane >> 2;
    int tg = lane & 3;
#pragma unroll
    for (int mt = 0; mt < 2; mt++) {
        int row0 = bm0 + wm * 32 + mt * 16 + g;
        int row1 = row0 + 8;
#pragma unroll
        for (int nt = 0; nt < 4; nt++) {
            int col = wn * 32 + nt * 8 + tg * 2;
            float b0 = bias[col], b1 = bias[col + 1];
            if (row0 < NN) {
                float v0 = c[mt][nt][0] + b0;  v0 = (v0 >= 0.f) ? v0 : NEG_SLOPE * v0;
                float v1 = c[mt][nt][1] + b1;  v1 = (v1 >= 0.f) ? v1 : NEG_SLOPE * v1;
                *reinterpret_cast<float2*>(g_h2 + (size_t)row0 * OUT2 + col) =
                    make_float2(v0, v1);
            }
            if (row1 < NN) {
                float v2 = c[mt][nt][2] + b0;  v2 = (v2 >= 0.f) ? v2 : NEG_SLOPE * v2;
                float v3 = c[mt][nt][3] + b1;  v3 = (v3 >= 0.f) ? v3 : NEG_SLOPE * v3;
                *reinterpret_cast<float2*>(g_h2 + (size_t)row1 * OUT2 + col) =
                    make_float2(v2, v3);
            }
        }
    }
}

// ---------------------------------------------------------------------------
// Output heads
// ---------------------------------------------------------------------------
__global__ void heads_kernel(const float* __restrict__ Wp, const float* __restrict__ bp,
                             const float* __restrict__ Wr, const float* __restrict__ br,
                             float* __restrict__ out) {
    int gid  = blockIdx.x * blockDim.x + threadIdx.x;
    int node = gid >> 5;
    int lane = gid & 31;
    if (node >= NN) return;

    float v0 = g_h2[(size_t)node * OUT2 + lane];
    float v1 = g_h2[(size_t)node * OUT2 + 32 + lane];

    float res[7];
#pragma unroll
    for (int o = 0; o < 7; o++) {
        float w0, w1, wlast, bb;
        if (o < 3) {
            w0 = Wp[lane * 3 + o];  w1 = Wp[(lane + 32) * 3 + o];
            wlast = Wp[64 * 3 + o]; bb = bp[o];
        } else {
            int oo = o - 3;
            w0 = Wr[lane * 4 + oo]; w1 = Wr[(lane + 32) * 4 + oo];
            wlast = Wr[64 * 4 + oo]; bb = br[oo];
        }
        float p = v0 * w0 + v1 * w1;
#pragma unroll
        for (int sft = 16; sft > 0; sft >>= 1)
            p += __shfl_down_sync(0xffffffffu, p, sft);
        res[o] = p + (float)node * wlast + bb;
    }
    if (lane == 0) {
        float r0 = res[3], r1 = res[4], r2 = res[5], r3 = res[6];
        float n = sqrtf(r0 * r0 + r1 * r1 + r2 * r2 + r3 * r3);
        n = fmaxf(n, 1e-12f);
        float* o = out + (size_t)node * 7;
        o[0] = res[0]; o[1] = res[1]; o[2] = res[2];
        o[3] = r0 / n; o[4] = r1 / n; o[5] = r2 / n; o[6] = r3 / n;
    }
}

// ---------------------------------------------------------------------------
// Launch sequence
// ---------------------------------------------------------------------------
extern "C" void kernel_launch(void* const* d_in, const int* in_sizes, int n_in,
                              void* d_out, int out_size) {
    const float* x       = (const float*)d_in[0];
    const float* W1_rel  = (const float*)d_in[1];
    const float* b1      = (const float*)d_in[2];
    const float* W1_root = (const float*)d_in[3];
    const float* W2_rel  = (const float*)d_in[4];
    const float* b2      = (const float*)d_in[5];
    const float* W2_root = (const float*)d_in[6];
    const float* Wp      = (const float*)d_in[7];
    const float* bp      = (const float*)d_in[8];
    const float* Wr      = (const float*)d_in[9];
    const float* br      = (const float*)d_in[10];
    const void*  ei      = d_in[11];
    float* out           = (float*)d_out;

    cudaFuncSetAttribute(gemm1_mma_kernel,
                         cudaFuncAttributeMaxDynamicSharedMemorySize, SMEM_G1);
    cudaFuncSetAttribute(gemm2_mma_kernel,
                         cudaFuncAttributeMaxDynamicSharedMemorySize, SMEM_G2);

    // CSR build
    detect_kernel<<<1, 256>>>((const int*)ei);
    zero_kernel<<<(NN + 255) / 256, 256>>>();
    hist_kernel<<<(EE + 255) / 256, 256>>>(ei);
    scan1_kernel<<<SCAN_B, 256>>>();
    scan2_kernel<<<1, 256>>>();
    scan3_kernel<<<SCAN_B, 256>>>();
    scatter_kernel<<<(EE + 255) / 256, 256>>>(ei);

    // prep
    wsplit1_kernel<<<(OUT1 * KH + 255) / 256, 256>>>(W1_root, W1_rel);
    wsplit2_kernel<<<(OUT2 * KH2 + 255) / 256, 256>>>(W2_root, W2_rel);
    node_prep_kernel<<<(NN + 255) / 256, 256>>>();

    // layer 1
    agg1_kernel<<<(NN * 32 + 255) / 256, 256>>>(x);
    {
        dim3 grid(OUT1 / 128, (NN + 127) / 128);
        gemm1_mma_kernel<<<grid, 256, SMEM_G1>>>(b1, W1_root, W1_rel);
    }

    // layer 2
    agg2_kernel<<<(NN * 32 + 255) / 256, 256>>>();
    gemm2_mma_kernel<<<(NN + 127) / 128, 256, SMEM_G2>>>(b2);

    // heads
    heads_kernel<<<(NN * 32 + 255) / 256, 256>>>(Wp, bp, Wr, br, out);
}

// round 16
// speedup vs baseline: 1.6785x; 1.3474x over previous
#include <cuda_runtime.h>
#include <cuda_bf16.h>
#include <cuda_fp16.h>
#include <math.h>
#include <cstdint>

// ---------------------------------------------------------------------------
// Problem constants
// ---------------------------------------------------------------------------
#define NN   50000
#define EE   200000
#define F0   512

// Layer 1: A1 = [x(512)|0|agg1(512)|0|pad] -> KH=1088, plain fp16.
// Idx cols zeroed; handled exactly in epilogue (fp32 rank-1 terms).
#define KH   1088
#define OUT1 256

// Layer 2: A2 = [h1/4 (256) | agg2/64 (256)] -> K2H=512, fp16, scale-
// compensated in W2 (rows x4 / x64). Idx columns handled in epilogue.
#define K2H  512
#define OUT2 64

// fp32 h1 buffer for agg2 gather (features only, no idx col)
#define H1S  256

#define NEG_SLOPE 0.01f
#define SC_H1  0.25f        // A2 cols [0,256) scale
#define SC_AG2 0.015625f    // A2 cols [256,512) scale (1/64)

// ---------------------------------------------------------------------------
// Scratch (static device globals)
// ---------------------------------------------------------------------------
__device__ __align__(256) __half g_a1h[(size_t)NN * KH];            // ~109 MB
__device__ __align__(256) __half g_w1h[(size_t)OUT1 * KH];          // fp16 W1, [n][k]
__device__ __align__(256) __half g_a2h[(size_t)NN * K2H];           // ~51 MB
__device__ __align__(256) __half g_w2h[(size_t)OUT2 * K2H];         // scale-compensated
__device__ __align__(256) float g_h1[(size_t)NN * H1S];             // ~51 MB
__device__ __align__(256) float g_h2[(size_t)NN * OUT2];            // ~13 MB
__device__ __align__(256) float g_aggidx[NN];    // softmax-agg of src idx
__device__ __align__(256) float g_aggidx2[NN];   // sum of src idx
__device__ int g_counts[NN];
__device__ int g_cursor[NN];
__device__ int g_offsets[NN + 1];
__device__ int g_csr[EE];
__device__ int g_blocksum[256];
__device__ int g_blockoff[256];
__device__ int g_idx_is32;

// ---------------------------------------------------------------------------
// Helpers
// ---------------------------------------------------------------------------
__device__ __forceinline__ uint32_t smem_u32(const void* p) {
    uint32_t a;
    asm("{ .reg .u64 t; cvta.to.shared.u64 t, %1; cvt.u32.u64 %0, t; }" : "=r"(a) : "l"(p));
    return a;
}

#define SW128(off) ((off) ^ (((off) >> 3) & 0x70))

__device__ __forceinline__ void ldmx4(uint32_t r[4], uint32_t addr) {
    asm volatile("ldmatrix.sync.aligned.m8n8.x4.shared.b16 {%0,%1,%2,%3}, [%4];"
        : "=r"(r[0]), "=r"(r[1]), "=r"(r[2]), "=r"(r[3]) : "r"(addr));
}

__device__ __forceinline__ void mma_f16(float c[4], const uint32_t a[4], const uint32_t b[2]) {
    asm volatile("mma.sync.aligned.m16n8k16.row.col.f32.f16.f16.f32 "
        "{%0,%1,%2,%3}, {%4,%5,%6,%7}, {%8,%9}, {%0,%1,%2,%3};"
        : "+f"(c[0]), "+f"(c[1]), "+f"(c[2]), "+f"(c[3])
        : "r"(a[0]), "r"(a[1]), "r"(a[2]), "r"(a[3]), "r"(b[0]), "r"(b[1]));
}

__device__ __forceinline__ void cp16(uint32_t saddr, const void* gaddr, int nbytes) {
    asm volatile("cp.async.cg.shared.global [%0], [%1], 16, %2;"
        :: "r"(saddr), "l"(gaddr), "r"(nbytes));
}
#define CP_COMMIT() asm volatile("cp.async.commit_group;" ::: "memory")
#define CP_WAIT(n)  asm volatile("cp.async.wait_group %0;" :: "n"(n) : "memory")

// softmax-accumulate 4 features (exp cannot overflow: x ~ N(0,1))
__device__ __forceinline__ void accum4(float* d, float* num, float4 v) {
    float e0 = __expf(v.x); d[0] += e0; num[0] = fmaf(e0, v.x, num[0]);
    float e1 = __expf(v.y); d[1] += e1; num[1] = fmaf(e1, v.y, num[1]);
    float e2 = __expf(v.z); d[2] += e2; num[2] = fmaf(e2, v.z, num[2]);
    float e3 = __expf(v.w); d[3] += e3; num[3] = fmaf(e3, v.w, num[3]);
}

// online-max softmax update (index feature, values up to 5e4)
__device__ __forceinline__ void upd_idx(float& m, float& d, float& n, float v) {
    float nm = fmaxf(m, v);
    float sc = __expf(m - nm);
    float ev = __expf(v - nm);
    d = d * sc + ev;
    n = n * sc + ev * v;
    m = nm;
}

// inclusive block scan over 256 threads; warp_part must be __shared__ int[8]
__device__ __forceinline__ int block_incl_scan_256(int v, int* warp_part) {
    int lane = threadIdx.x & 31, w = threadIdx.x >> 5;
    int x = v;
#pragma unroll
    for (int o = 1; o < 32; o <<= 1) {
        int u = __shfl_up_sync(0xffffffffu, x, o);
        if (lane >= o) x += u;
    }
    if (lane == 31) warp_part[w] = x;
    __syncthreads();
    if (w == 0) {
        int y = (lane < 8) ? warp_part[lane] : 0;
#pragma unroll
        for (int o = 1; o < 8; o <<= 1) {
            int u = __shfl_up_sync(0xffffffffu, y, o);
            if (lane >= o) y += u;
        }
        if (lane < 8) warp_part[lane] = y;
    }
    __syncthreads();
    return x + ((w > 0) ? warp_part[w - 1] : 0);
}

// ---------------------------------------------------------------------------
// edge_index dtype detection (int64 vs int32-demoted)
// ---------------------------------------------------------------------------
__global__ void detect_kernel(const int* ei_words) {
    __shared__ int acc;
    if (threadIdx.x == 0) acc = 0;
    __syncthreads();
    int v = ei_words[2 * threadIdx.x + 1];
    if (v != 0) atomicOr(&acc, 1);
    __syncthreads();
    if (threadIdx.x == 0) g_idx_is32 = acc;
}

__device__ __forceinline__ int edge_val(const void* ei, int idx) {
    if (g_idx_is32) return ((const int*)ei)[idx];
    return (int)((const long long*)ei)[idx];
}

// ---------------------------------------------------------------------------
// CSR build (by destination)
// ---------------------------------------------------------------------------
__global__ void zero_kernel() {
    int i = blockIdx.x * blockDim.x + threadIdx.x;
    if (i < NN) { g_counts[i] = 0; g_cursor[i] = 0; }
}

__global__ void hist_kernel(const void* ei) {
    int e = blockIdx.x * blockDim.x + threadIdx.x;
    if (e >= EE) return;
    int d = edge_val(ei, EE + e);
    if ((unsigned)d < NN) atomicAdd(&g_counts[d], 1);
}

#define SCAN_B 196   // ceil(50000/256)

__global__ void scan1_kernel() {
    __shared__ int wp[8];
    int i = blockIdx.x * 256 + threadIdx.x;
    int v = (i < NN) ? g_counts[i] : 0;
    int incl = block_incl_scan_256(v, wp);
    if (threadIdx.x == 255) g_blocksum[blockIdx.x] = incl;
}

__global__ void scan2_kernel() {
    __shared__ int wp[8];
    int t = threadIdx.x;
    int v = (t < SCAN_B) ? g_blocksum[t] : 0;
    int incl = block_incl_scan_256(v, wp);
    if (t < SCAN_B) g_blockoff[t] = incl - v;
    if (t == 255) g_offsets[NN] = incl;
}

__global__ void scan3_kernel() {
    __shared__ int wp[8];
    int i = blockIdx.x * 256 + threadIdx.x;
    int v = (i < NN) ? g_counts[i] : 0;
    int incl = block_incl_scan_256(v, wp);
    if (i < NN) g_offsets[i] = incl - v + g_blockoff[blockIdx.x];
}

__global__ void scatter_kernel(const void* ei) {
    int e = blockIdx.x * blockDim.x + threadIdx.x;
    if (e >= EE) return;
    int s = edge_val(ei, e);
    int d = edge_val(ei, EE + e);
    if ((unsigned)d >= NN) return;
    int pos = g_offsets[d] + atomicAdd(&g_cursor[d], 1);
    g_csr[pos] = s;
}

// ---------------------------------------------------------------------------
// Weight prep (plain fp16, [n][k] K-major; W2 scale-compensated)
// ---------------------------------------------------------------------------
__global__ void wsplit1_kernel(const float* __restrict__ W1_root,
                               const float* __restrict__ W1_rel) {
    int idx = blockIdx.x * blockDim.x + threadIdx.x;
    if (idx >= OUT1 * KH) return;
    int n = idx / KH, k = idx - n * KH;
    float w = 0.f;
    if (k < 513)       w = W1_root[k * OUT1 + n];
    else if (k < 1026) w = W1_rel[(k - 513) * OUT1 + n];
    g_w1h[(size_t)n * KH + k] = __float2half(w);
}

__global__ void wsplit2_kernel(const float* __restrict__ W2_root,
                               const float* __restrict__ W2_rel) {
    int idx = blockIdx.x * blockDim.x + threadIdx.x;
    if (idx >= OUT2 * K2H) return;
    int n = idx / K2H, k = idx - n * K2H;
    // compensate A2 scaling: cols [0,256) carry h1/4, cols [256,512) agg2/64
    float w = (k < 256) ? W2_root[k * OUT2 + n] * 4.0f
                        : W2_rel[(k - 256) * OUT2 + n] * 64.0f;
    g_w2h[(size_t)n * K2H + k] = __float2half(w);
}

// ---------------------------------------------------------------------------
// Aggregation 1: per-destination softmax aggregation over 513 features.
// float4 gather (4 x LDG.128 per edge per lane) + 2-edge unroll.
// Lane owns features f = t*128 + lane*4 + j (t<4, j<4).
// Emits fp16 A1 row [x|0|agg|0|pad] and fp32 g_aggidx.
// ---------------------------------------------------------------------------
__global__ void agg1_kernel(const float* __restrict__ x) {
    int gid  = blockIdx.x * blockDim.x + threadIdx.x;
    int node = gid >> 5;
    int lane = gid & 31;
    if (node >= NN) return;

    int beg = g_offsets[node], end = g_offsets[node + 1];

    float d[16], num[16];
#pragma unroll
    for (int r = 0; r < 16; r++) { d[r] = 0.f; num[r] = 0.f; }
    float mi = -1e30f, di = 0.f, numi = 0.f;

    int e = beg;
    for (; e + 1 < end; e += 2) {
        int s0 = g_csr[e], s1 = g_csr[e + 1];
        const float4* p0 = reinterpret_cast<const float4*>(x + (size_t)s0 * F0) + lane;
        const float4* p1 = reinterpret_cast<const float4*>(x + (size_t)s1 * F0) + lane;
        float4 a0 = __ldg(p0),      a1 = __ldg(p0 + 32),
               a2 = __ldg(p0 + 64), a3 = __ldg(p0 + 96);
        float4 b0 = __ldg(p1),      b1 = __ldg(p1 + 32),
               b2 = __ldg(p1 + 64), b3 = __ldg(p1 + 96);
        accum4(d + 0,  num + 0,  a0); accum4(d + 4,  num + 4,  a1);
        accum4(d + 8,  num + 8,  a2); accum4(d + 12, num + 12, a3);
        accum4(d + 0,  num + 0,  b0); accum4(d + 4,  num + 4,  b1);
        accum4(d + 8,  num + 8,  b2); accum4(d + 12, num + 12, b3);
        if (lane == 0) {
            upd_idx(mi, di, numi, (float)s0);
            upd_idx(mi, di, numi, (float)s1);
        }
    }
    if (e < end) {
        int s0 = g_csr[e];
        const float4* p0 = reinterpret_cast<const float4*>(x + (size_t)s0 * F0) + lane;
        float4 a0 = __ldg(p0),      a1 = __ldg(p0 + 32),
               a2 = __ldg(p0 + 64), a3 = __ldg(p0 + 96);
        accum4(d + 0,  num + 0,  a0); accum4(d + 4,  num + 4,  a1);
        accum4(d + 8,  num + 8,  a2); accum4(d + 12, num + 12, a3);
        if (lane == 0) upd_idx(mi, di, numi, (float)s0);
    }

    __half* row = g_a1h + (size_t)node * KH;
    const float4* xi = reinterpret_cast<const float4*>(x + (size_t)node * F0) + lane;
#pragma unroll
    for (int t = 0; t < 4; t++) {
        float4 v = __ldg(xi + t * 32);
        *reinterpret_cast<__half2*>(row + t * 128 + lane * 4)     = __floats2half2_rn(v.x, v.y);
        *reinterpret_cast<__half2*>(row + t * 128 + lane * 4 + 2) = __floats2half2_rn(v.z, v.w);
    }
    bool nonempty = (end > beg);
#pragma unroll
    for (int t = 0; t < 4; t++)
#pragma unroll
        for (int j = 0; j < 4; j++) {
            int f = t * 128 + lane * 4 + j;
            float o = nonempty ? (num[t * 4 + j] / fmaxf(d[t * 4 + j], 1e-16f)) : 0.f;
            row[513 + f] = __float2half(o);
        }
    if (lane == 0) {
        float o = nonempty ? (numi / fmaxf(di, 1e-16f)) : 0.f;
        g_aggidx[node] = o;
        row[512]  = __float2half(0.f);
        row[1025] = __float2half(0.f);
    }
    __half z = __float2half(0.f);
    for (int f = 1026 + lane; f < KH; f += 32) row[f] = z;
}

// ---------------------------------------------------------------------------
// gemm1 (mma.sync fp16 single-pass, 3-stage cp.async ring):
// h1 = leaky(A1*W1 + b1 + node*W_root[512] + aggidx*W_rel[512]).
// CTA 128x128, 8 warps (4m x 2n), BK=64 (17 chunks).
// ---------------------------------------------------------------------------
#define S1_A  0
#define S1_B  16384
#define BUF1  32768
#define SMEM_G1 (3 * BUF1)

__device__ __forceinline__ void g1_prefetch(uint32_t base, int bm0, int bn0,
                                            int k0, int tid) {
#pragma unroll
    for (int t = 0; t < 4; t++) {
        int item = tid + t * 256;
        int r = item >> 3, q = item & 7;
        int grow = bm0 + r;
        int ok = (grow < NN) ? 16 : 0;
        int crow = (grow < NN) ? grow : (NN - 1);
        const char* p = (const char*)(g_a1h + (size_t)crow * KH + k0 + q * 8);
        cp16(base + S1_A + SW128(r * 128 + q * 16), p, ok);
    }
#pragma unroll
    for (int t = 0; t < 4; t++) {
        int item = tid + t * 256;
        int n = item >> 3, q = item & 7;
        const char* p = (const char*)(g_w1h + (size_t)(bn0 + n) * KH + k0 + q * 8);
        cp16(base + S1_B + SW128(n * 128 + q * 16), p, 16);
    }
}

__device__ __forceinline__ void store_h1(int row, int col, float v0, float v1) {
    *reinterpret_cast<float2*>(g_h1 + (size_t)row * H1S + col) = make_float2(v0, v1);
    // A2 cols [0,256): h1/4 (range-safe fp16; compensated by W2_root x4)
    *reinterpret_cast<__half2*>(g_a2h + (size_t)row * K2H + col) =
        __floats2half2_rn(v0 * SC_H1, v1 * SC_H1);
}

__global__ __launch_bounds__(256, 1) void gemm1_mma_kernel(
    const float* __restrict__ bias,
    const float* __restrict__ W1_root,
    const float* __restrict__ W1_rel)
{
    extern __shared__ __align__(1024) char sm[];
    uint32_t sb = smem_u32(sm);
    int tid  = threadIdx.x;
    int lane = tid & 31;
    int wid  = tid >> 5;
    int wm = wid & 3;
    int wn = wid >> 2;
    int bm0 = blockIdx.y * 128;
    int bn0 = blockIdx.x * 128;

    float c[2][8][4];
#pragma unroll
    for (int i = 0; i < 2; i++)
#pragma unroll
        for (int j = 0; j < 8; j++)
#pragma unroll
            for (int q = 0; q < 4; q++) c[i][j][q] = 0.f;

    int a_row  = wm * 32 + (lane & 15);
    int a_koff = (lane >> 4) * 16;
    int b_rowb = wn * 64 + ((lane >> 4) << 3) + (lane & 7);
    int b_koff = ((lane >> 3) & 1) * 16;

    g1_prefetch(sb,        bm0, bn0, 0,  tid); CP_COMMIT();
    g1_prefetch(sb + BUF1, bm0, bn0, 64, tid); CP_COMMIT();

    for (int ch = 0; ch < 17; ch++) {
        if (ch + 2 < 17) {
            g1_prefetch(sb + ((ch + 2) % 3) * BUF1, bm0, bn0, (ch + 2) * 64, tid);
            CP_COMMIT();
            CP_WAIT(2);
        } else if (ch + 1 < 17) {
            CP_WAIT(1);
        } else {
            CP_WAIT(0);
        }
        __syncthreads();

        uint32_t cb = sb + (ch % 3) * BUF1;
#pragma unroll
        for (int ks = 0; ks < 4; ks++) {
            int kb = ks * 32;
            uint32_t a[2][4];
#pragma unroll
            for (int mt = 0; mt < 2; mt++) {
                uint32_t off = SW128((a_row + mt * 16) * 128 + kb + a_koff);
                ldmx4(a[mt], cb + S1_A + off);
            }
            uint32_t bh[8][2];
#pragma unroll
            for (int p2 = 0; p2 < 4; p2++) {
                uint32_t off = SW128((b_rowb + p2 * 16) * 128 + kb + b_koff);
                uint32_t r4[4];
                ldmx4(r4, cb + S1_B + off);
                bh[p2 * 2][0] = r4[0]; bh[p2 * 2][1] = r4[1];
                bh[p2 * 2 + 1][0] = r4[2]; bh[p2 * 2 + 1][1] = r4[3];
            }
#pragma unroll
            for (int mt = 0; mt < 2; mt++)
#pragma unroll
                for (int nt = 0; nt < 8; nt++)
                    mma_f16(c[mt][nt], a[mt], bh[nt]);
        }
        __syncthreads();
    }

    int g  = lane >> 2;
    int tg = lane & 3;
#pragma unroll
    for (int mt = 0; mt < 2; mt++) {
        int row0 = bm0 + wm * 32 + mt * 16 + g;
        int row1 = row0 + 8;
        float ai0 = (row0 < NN) ? g_aggidx[row0] : 0.f;
        float ai1 = (row1 < NN) ? g_aggidx[row1] : 0.f;
#pragma unroll
        for (int nt = 0; nt < 8; nt++) {
            int col = bn0 + wn * 64 + nt * 8 + tg * 2;
            float b0 = bias[col], b1 = bias[col + 1];
            float wr0 = W1_root[512 * OUT1 + col], wr1 = W1_root[512 * OUT1 + col + 1];
            float we0 = W1_rel[512 * OUT1 + col],  we1 = W1_rel[512 * OUT1 + col + 1];
            if (row0 < NN) {
                float v0 = c[mt][nt][0] + b0 + (float)row0 * wr0 + ai0 * we0;
                float v1 = c[mt][nt][1] + b1 + (float)row0 * wr1 + ai0 * we1;
                v0 = (v0 >= 0.f) ? v0 : NEG_SLOPE * v0;
                v1 = (v1 >= 0.f) ? v1 : NEG_SLOPE * v1;
                store_h1(row0, col, v0, v1);
            }
            if (row1 < NN) {
                float v2 = c[mt][nt][2] + b0 + (float)row1 * wr0 + ai1 * we0;
                float v3 = c[mt][nt][3] + b1 + (float)row1 * wr1 + ai1 * we1;
                v2 = (v2 >= 0.f) ? v2 : NEG_SLOPE * v2;
                v3 = (v3 >= 0.f) ? v3 : NEG_SLOPE * v3;
                store_h1(row1, col, v2, v3);
            }
        }
    }
}

// ---------------------------------------------------------------------------
// Aggregation 2: per-destination sum over 256 h1 features (fp32 gather,
// float4 x2 per edge per lane, 2-edge unroll). Sum of src indices computed
// arithmetically (no load). Writes fp16 (scaled 1/64) into g_a2h cols
// [256,512) and fp32 g_aggidx2.
// ---------------------------------------------------------------------------
__global__ void agg2_kernel() {
    int gid  = blockIdx.x * blockDim.x + threadIdx.x;
    int node = gid >> 5;
    int lane = gid & 31;
    if (node >= NN) return;

    int beg = g_offsets[node], end = g_offsets[node + 1];
    float s[8];
#pragma unroll
    for (int r = 0; r < 8; r++) s[r] = 0.f;
    float sidx = 0.f;

    int e = beg;
    for (; e + 1 < end; e += 2) {
        int s0 = g_csr[e], s1 = g_csr[e + 1];
        const float4* p0 = reinterpret_cast<const float4*>(g_h1 + (size_t)s0 * H1S) + lane;
        const float4* p1 = reinterpret_cast<const float4*>(g_h1 + (size_t)s1 * H1S) + lane;
        float4 a0 = __ldg(p0), a1 = __ldg(p0 + 32);
        float4 b0 = __ldg(p1), b1 = __ldg(p1 + 32);
        s[0] += a0.x + b0.x; s[1] += a0.y + b0.y;
        s[2] += a0.z + b0.z; s[3] += a0.w + b0.w;
        s[4] += a1.x + b1.x; s[5] += a1.y + b1.y;
        s[6] += a1.z + b1.z; s[7] += a1.w + b1.w;
        sidx += (float)s0 + (float)s1;
    }
    if (e < end) {
        int s0 = g_csr[e];
        const float4* p0 = reinterpret_cast<const float4*>(g_h1 + (size_t)s0 * H1S) + lane;
        float4 a0 = __ldg(p0), a1 = __ldg(p0 + 32);
        s[0] += a0.x; s[1] += a0.y; s[2] += a0.z; s[3] += a0.w;
        s[4] += a1.x; s[5] += a1.y; s[6] += a1.z; s[7] += a1.w;
        sidx += (float)s0;
    }

    __half* row = g_a2h + (size_t)node * K2H;
#pragma unroll
    for (int t = 0; t < 2; t++) {
        int f = t * 128 + lane * 4;
        *reinterpret_cast<__half2*>(row + 256 + f) =
            __floats2half2_rn(s[t * 4 + 0] * SC_AG2, s[t * 4 + 1] * SC_AG2);
        *reinterpret_cast<__half2*>(row + 256 + f + 2) =
            __floats2half2_rn(s[t * 4 + 2] * SC_AG2, s[t * 4 + 3] * SC_AG2);
    }
    if (lane == 0) g_aggidx2[node] = sidx;
}

// ---------------------------------------------------------------------------
// gemm2 (mma.sync fp16 single-pass, double-buffered):
// h2 = leaky(A2*W2 + b2 + node*W2_root[256] + sidx*W2_rel[256]) -> g_h2.
// CTA 128x64, 8 warps (4m x 2n), warp 32x32, BK=64 (8 chunks).
// ---------------------------------------------------------------------------
#define S2_A 0
#define S2_B 16384
#define BUF2 24576
#define SMEM_G2 (2 * BUF2)

__device__ __forceinline__ void g2_prefetch(uint32_t base, int bm0, int k0, int tid) {
#pragma unroll
    for (int t = 0; t < 4; t++) {
        int item = tid + t * 256;
        int r = item >> 3, q = item & 7;
        int grow = bm0 + r;
        int ok = (grow < NN) ? 16 : 0;
        int crow = (grow < NN) ? grow : (NN - 1);
        const char* p = (const char*)(g_a2h + (size_t)crow * K2H + k0 + q * 8);
        cp16(base + S2_A + SW128(r * 128 + q * 16), p, ok);
    }
#pragma unroll
    for (int t = 0; t < 2; t++) {
        int item = tid + t * 256;
        int n = item >> 3, q = item & 7;
        const char* p = (const char*)(g_w2h + (size_t)n * K2H + k0 + q * 8);
        cp16(base + S2_B + SW128(n * 128 + q * 16), p, 16);
    }
}

__global__ __launch_bounds__(256, 1) void gemm2_mma_kernel(
    const float* __restrict__ bias,
    const float* __restrict__ W2_root,
    const float* __restrict__ W2_rel)
{
    extern __shared__ __align__(1024) char sm[];
    uint32_t sb = smem_u32(sm);
    int tid  = threadIdx.x;
    int lane = tid & 31;
    int wid  = tid >> 5;
    int wm = wid & 3;
    int wn = wid >> 2;
    int bm0 = blockIdx.x * 128;

    float c[2][4][4];
#pragma unroll
    for (int i = 0; i < 2; i++)
#pragma unroll
        for (int j = 0; j < 4; j++)
#pragma unroll
            for (int q = 0; q < 4; q++) c[i][j][q] = 0.f;

    int a_row  = wm * 32 + (lane & 15);
    int a_koff = (lane >> 4) * 16;
    int b_rowb = wn * 32 + ((lane >> 4) << 3) + (lane & 7);
    int b_koff = ((lane >> 3) & 1) * 16;

    g2_prefetch(sb, bm0, 0, tid);
    CP_COMMIT();

    for (int ch = 0; ch < 8; ch++) {
        if (ch < 7) {
            g2_prefetch(sb + ((ch + 1) & 1) * BUF2, bm0, (ch + 1) * 64, tid);
            CP_COMMIT();
            CP_WAIT(1);
        } else {
            CP_WAIT(0);
        }
        __syncthreads();

        uint32_t cb = sb + (ch & 1) * BUF2;
#pragma unroll
        for (int ks = 0; ks < 4; ks++) {
            int kb = ks * 32;
            uint32_t a[2][4];
#pragma unroll
            for (int mt = 0; mt < 2; mt++) {
                uint32_t off = SW128((a_row + mt * 16) * 128 + kb + a_koff);
                ldmx4(a[mt], cb + S2_A + off);
            }
            uint32_t bh[4][2];
#pragma unroll
            for (int p2 = 0; p2 < 2; p2++) {
                uint32_t off = SW128((b_rowb + p2 * 16) * 128 + kb + b_koff);
                uint32_t r4[4];
                ldmx4(r4, cb + S2_B + off);
                bh[p2 * 2][0] = r4[0]; bh[p2 * 2][1] = r4[1];
                bh[p2 * 2 + 1][0] = r4[2]; bh[p2 * 2 + 1][1] = r4[3];
            }
#pragma unroll
            for (int mt = 0; mt < 2; mt++)
#pragma unroll
                for (int nt = 0; nt < 4; nt++)
                    mma_f16(c[mt][nt], a[mt], bh[nt]);
        }
        __syncthreads();
    }

    int g  = lane >> 2;
    int tg = lane & 3;
#pragma unroll
    for (int mt = 0; mt < 2; mt++) {
        int row0 = bm0 + wm * 32 + mt * 16 + g;
        int row1 = row0 + 8;
        float ai0 = (row0 < NN) ? g_aggidx2[row0] : 0.f;
        float ai1 = (row1 < NN) ? g_aggidx2[row1] : 0.f;
#pragma unroll
        for (int nt = 0; nt < 4; nt++) {
            int col = wn * 32 + nt * 8 + tg * 2;
            float b0 = bias[col], b1 = bias[col + 1];
            float wr0 = W2_root[256 * OUT2 + col], wr1 = W2_root[256 * OUT2 + col + 1];
            float we0 = W2_rel[256 * OUT2 + col],  we1 = W2_rel[256 * OUT2 + col + 1];
            if (row0 < NN) {
                float v0 = c[mt][nt][0] + b0 + (float)row0 * wr0 + ai0 * we0;
                float v1 = c[mt][nt][1] + b1 + (float)row0 * wr1 + ai0 * we1;
                v0 = (v0 >= 0.f) ? v0 : NEG_SLOPE * v0;
                v1 = (v1 >= 0.f) ? v1 : NEG_SLOPE * v1;
                *reinterpret_cast<float2*>(g_h2 + (size_t)row0 * OUT2 + col) =
                    make_float2(v0, v1);
            }
            if (row1 < NN) {
                float v2 = c[mt][nt][2] + b0 + (float)row1 * wr0 + ai1 * we0;
                float v3 = c[mt][nt][3] + b1 + (float)row1 * wr1 + ai1 * we1;
                v2 = (v2 >= 0.f) ? v2 : NEG_SLOPE * v2;
                v3 = (v3 >= 0.f) ? v3 : NEG_SLOPE * v3;
                *reinterpret_cast<float2*>(g_h2 + (size_t)row1 * OUT2 + col) =
                    make_float2(v2, v3);
            }
        }
    }
}

// ---------------------------------------------------------------------------
// Output heads
// ---------------------------------------------------------------------------
__global__ void heads_kernel(const float* __restrict__ Wp, const float* __restrict__ bp,
                             const float* __restrict__ Wr, const float* __restrict__ br,
                             float* __restrict__ out) {
    int gid  = blockIdx.x * blockDim.x + threadIdx.x;
    int node = gid >> 5;
    int lane = gid & 31;
    if (node >= NN) return;

    float v0 = g_h2[(size_t)node * OUT2 + lane];
    float v1 = g_h2[(size_t)node * OUT2 + 32 + lane];

    float res[7];
#pragma unroll
    for (int o = 0; o < 7; o++) {
        float w0, w1, wlast, bb;
        if (o < 3) {
            w0 = Wp[lane * 3 + o];  w1 = Wp[(lane + 32) * 3 + o];
            wlast = Wp[64 * 3 + o]; bb = bp[o];
        } else {
            int oo = o - 3;
            w0 = Wr[lane * 4 + oo]; w1 = Wr[(lane + 32) * 4 + oo];
            wlast = Wr[64 * 4 + oo]; bb = br[oo];
        }
        float p = v0 * w0 + v1 * w1;
#pragma unroll
        for (int sft = 16; sft > 0; sft >>= 1)
            p += __shfl_down_sync(0xffffffffu, p, sft);
        res[o] = p + (float)node * wlast + bb;
    }
    if (lane == 0) {
        float r0 = res[3], r1 = res[4], r2 = res[5], r3 = res[6];
        float n = sqrtf(r0 * r0 + r1 * r1 + r2 * r2 + r3 * r3);
        n = fmaxf(n, 1e-12f);
        float* o = out + (size_t)node * 7;
        o[0] = res[0]; o[1] = res[1]; o[2] = res[2];
        o[3] = r0 / n; o[4] = r1 / n; o[5] = r2 / n; o[6] = r3 / n;
    }
}

// ---------------------------------------------------------------------------
// Launch sequence
// ---------------------------------------------------------------------------
extern "C" void kernel_launch(void* const* d_in, const int* in_sizes, int n_in,
                              void* d_out, int out_size) {
    const float* x       = (const float*)d_in[0];
    const float* W1_rel  = (const float*)d_in[1];
    const float* b1      = (const float*)d_in[2];
    const float* W1_root = (const float*)d_in[3];
    const float* W2_rel  = (const float*)d_in[4];
    const float* b2      = (const float*)d_in[5];
    const float* W2_root = (const float*)d_in[6];
    const float* Wp      = (const float*)d_in[7];
    const float* bp      = (const float*)d_in[8];
    const float* Wr      = (const float*)d_in[9];
    const float* br      = (const float*)d_in[10];
    const void*  ei      = d_in[11];
    float* out           = (float*)d_out;

    cudaFuncSetAttribute(gemm1_mma_kernel,
                         cudaFuncAttributeMaxDynamicSharedMemorySize, SMEM_G1);
    cudaFuncSetAttribute(gemm2_mma_kernel,
                         cudaFuncAttributeMaxDynamicSharedMemorySize, SMEM_G2);

    // CSR build
    detect_kernel<<<1, 256>>>((const int*)ei);
    zero_kernel<<<(NN + 255) / 256, 256>>>();
    hist_kernel<<<(EE + 255) / 256, 256>>>(ei);
    scan1_kernel<<<SCAN_B, 256>>>();
    scan2_kernel<<<1, 256>>>();
    scan3_kernel<<<SCAN_B, 256>>>();
    scatter_kernel<<<(EE + 255) / 256, 256>>>(ei);

    // prep
    wsplit1_kernel<<<(OUT1 * KH + 255) / 256, 256>>>(W1_root, W1_rel);
    wsplit2_kernel<<<(OUT2 * K2H + 255) / 256, 256>>>(W2_root, W2_rel);

    // layer 1
    agg1_kernel<<<(NN * 32 + 255) / 256, 256>>>(x);
    {
        dim3 grid(OUT1 / 128, (NN + 127) / 128);
        gemm1_mma_kernel<<<grid, 256, SMEM_G1>>>(b1, W1_root, W1_rel);
    }

    // layer 2
    agg2_kernel<<<(NN * 32 + 255) / 256, 256>>>();
    gemm2_mma_kernel<<<(NN + 127) / 128, 256, SMEM_G2>>>(b2, W2_root, W2_rel);

    // heads
    heads_kernel<<<(NN * 32 + 255) / 256, 256>>>(Wp, bp, Wr, br, out);
}